// round 2
// baseline (speedup 1.0000x reference)
#include <cuda_runtime.h>
#include <math.h>

#define S_LEN 2048
#define DM    2048
#define QH    32
#define KVH   8
#define DH    64
#define KV_W  (2 * KVH * DH)   // 1024

// ---------------- scratch (allocation-free: __device__ globals) ----------------
__device__ float g_Q[S_LEN * DM];        // 16 MB: Q projections (rope'd in place)
__device__ float g_KV[S_LEN * KV_W];     //  8 MB: [K(512) | V(512)] per row
__device__ float g_attn[S_LEN * DM];     // 16 MB: attention output

// ==============================================================================
// SGEMM: C[M,N] = A[M,K] @ B[N,K]^T + bias[N]
// 128x128 block tile, BK=8, 256 threads, 8x8 per-thread register tile.
// All problem dims are multiples of 128/8 -> no bounds checks.
// ==============================================================================
__global__ __launch_bounds__(256, 2)
void sgemm_nt_bias(const float* __restrict__ A, const float* __restrict__ B,
                   const float* __restrict__ bias, float* __restrict__ C,
                   int M, int N, int K)
{
    __shared__ __align__(16) float As[8][128];
    __shared__ __align__(16) float Bs[8][128];

    const int tid  = threadIdx.x;
    const int brow = blockIdx.y * 128;
    const int bcol = blockIdx.x * 128;

    const int lr = tid >> 1;          // 0..127 : tile row loaded by this thread
    const int lk = (tid & 1) << 2;    // 0 or 4 : k offset (float4)
    const int tm = (tid >> 4) << 3;   // per-thread output rows
    const int tn = (tid & 15) << 3;   // per-thread output cols

    const float* Ap = A + (size_t)(brow + lr) * K + lk;
    const float* Bp = B + (size_t)(bcol + lr) * K + lk;

    float acc[8][8];
#pragma unroll
    for (int i = 0; i < 8; i++)
#pragma unroll
        for (int j = 0; j < 8; j++) acc[i][j] = 0.0f;

    for (int k0 = 0; k0 < K; k0 += 8) {
        float4 a4 = *(const float4*)Ap;
        float4 b4 = *(const float4*)Bp;
        As[lk + 0][lr] = a4.x; As[lk + 1][lr] = a4.y;
        As[lk + 2][lr] = a4.z; As[lk + 3][lr] = a4.w;
        Bs[lk + 0][lr] = b4.x; Bs[lk + 1][lr] = b4.y;
        Bs[lk + 2][lr] = b4.z; Bs[lk + 3][lr] = b4.w;
        __syncthreads();

#pragma unroll
        for (int k = 0; k < 8; k++) {
            float4 a0 = *(const float4*)&As[k][tm];
            float4 a1 = *(const float4*)&As[k][tm + 4];
            float4 b0 = *(const float4*)&Bs[k][tn];
            float4 b1 = *(const float4*)&Bs[k][tn + 4];
            const float ar[8] = {a0.x, a0.y, a0.z, a0.w, a1.x, a1.y, a1.z, a1.w};
            const float br[8] = {b0.x, b0.y, b0.z, b0.w, b1.x, b1.y, b1.z, b1.w};
#pragma unroll
            for (int i = 0; i < 8; i++)
#pragma unroll
                for (int j = 0; j < 8; j++)
                    acc[i][j] = fmaf(ar[i], br[j], acc[i][j]);
        }
        __syncthreads();
        Ap += 8;
        Bp += 8;
    }

#pragma unroll
    for (int i = 0; i < 8; i++) {
        float* Cp = C + (size_t)(brow + tm + i) * N + bcol + tn;
#pragma unroll
        for (int j = 0; j < 8; j += 4) {
            float4 v;
            v.x = acc[i][j + 0] + bias[bcol + tn + j + 0];
            v.y = acc[i][j + 1] + bias[bcol + tn + j + 1];
            v.z = acc[i][j + 2] + bias[bcol + tn + j + 2];
            v.w = acc[i][j + 3] + bias[bcol + tn + j + 3];
            *(float4*)(Cp + j) = v;
        }
    }
}

// ==============================================================================
// RoPE (interleaved pairs), in place. One thread per (s, head, pair).
// freq computed in double to match the fp32-rounded exact value jax produces.
// ==============================================================================
__global__ void rope_kernel(float* __restrict__ X, int H, int rowstride)
{
    int idx = blockIdx.x * blockDim.x + threadIdx.x;
    int total = S_LEN * H * (DH / 2);
    if (idx >= total) return;

    int j = idx & 31;           // pair index 0..31
    int t = idx >> 5;
    int h = t % H;
    int s = t / H;

    float freq  = (float)pow(10000.0, -(double)j / 32.0);
    float theta = (float)s * freq;
    float sn, cs;
    sincosf(theta, &sn, &cs);

    float* p = X + (size_t)s * rowstride + h * DH + 2 * j;
    float x1 = p[0], x2 = p[1];
    p[0] = x1 * cs - x2 * sn;
    p[1] = x1 * sn + x2 * cs;
}

// ==============================================================================
// Flash attention, fp32, no mask. One block per (q-tile of 64 rows, head).
// 256 threads as 16x16; each thread owns a 4x4 fragment.
// smem: Qs | Ks(reused as Ps) | Vs, each 64 x 68 floats (pad keeps 16B align).
// ==============================================================================
#define FPAD 68

__global__ __launch_bounds__(256)
void flash_attn(const float* __restrict__ Q, const float* __restrict__ KV,
                float* __restrict__ O)
{
    extern __shared__ float sm[];
    float* Qs = sm;                  // [64][FPAD]
    float* Ks = sm + 64 * FPAD;      // [64][FPAD], reused for P
    float* Vs = sm + 2 * 64 * FPAD;  // [64][FPAD]

    const int qt  = blockIdx.x;
    const int h   = blockIdx.y;
    const int hk  = h >> 2;          // grouped KV head
    const int tid = threadIdx.x;
    const int tx  = tid & 15;
    const int ty  = tid >> 4;
    const int r0  = ty << 2;         // 4 query rows
    const int c0  = tx << 2;         // 4 key cols / 4 output dims

    // ---- load Q tile, pre-scaled by 1/sqrt(64) ----
    {
        const float* src = Q + (size_t)(qt * 64) * DM + h * DH;
        for (int i = tid; i < 64 * 16; i += 256) {
            int r = i >> 4, c = (i & 15) << 2;
            float4 v = *(const float4*)(src + (size_t)r * DM + c);
            v.x *= 0.125f; v.y *= 0.125f; v.z *= 0.125f; v.w *= 0.125f;
            *(float4*)(Qs + r * FPAD + c) = v;
        }
    }

    float m_i[4], l_i[4], acc[4][4];
#pragma unroll
    for (int i = 0; i < 4; i++) {
        m_i[i] = -1e30f;
        l_i[i] = 0.0f;
#pragma unroll
        for (int j = 0; j < 4; j++) acc[i][j] = 0.0f;
    }

    for (int kt = 0; kt < 32; kt++) {
        __syncthreads();  // previous iteration done reading Ps/Vs (and 1st: no-op)

        // ---- load K, V tiles ----
        const float* ksrc = KV + (size_t)(kt * 64) * KV_W + hk * DH;
        const float* vsrc = ksrc + KVH * DH;  // V offset 512
        for (int i = tid; i < 64 * 16; i += 256) {
            int r = i >> 4, c = (i & 15) << 2;
            *(float4*)(Ks + r * FPAD + c) = *(const float4*)(ksrc + (size_t)r * KV_W + c);
            *(float4*)(Vs + r * FPAD + c) = *(const float4*)(vsrc + (size_t)r * KV_W + c);
        }
        __syncthreads();

        // ---- S = (Q*scale) @ K^T, 4x4 fragment ----
        float s[4][4];
#pragma unroll
        for (int i = 0; i < 4; i++)
#pragma unroll
            for (int j = 0; j < 4; j++) s[i][j] = 0.0f;

#pragma unroll 4
        for (int d = 0; d < 64; d += 4) {
            float4 q4[4], k4[4];
#pragma unroll
            for (int i = 0; i < 4; i++) q4[i] = *(const float4*)(Qs + (r0 + i) * FPAD + d);
#pragma unroll
            for (int j = 0; j < 4; j++) k4[j] = *(const float4*)(Ks + (c0 + j) * FPAD + d);
#pragma unroll
            for (int i = 0; i < 4; i++) {
                const float qa[4] = {q4[i].x, q4[i].y, q4[i].z, q4[i].w};
#pragma unroll
                for (int j = 0; j < 4; j++) {
                    const float ka[4] = {k4[j].x, k4[j].y, k4[j].z, k4[j].w};
#pragma unroll
                    for (int dd = 0; dd < 4; dd++)
                        s[i][j] = fmaf(qa[dd], ka[dd], s[i][j]);
                }
            }
        }

        // ---- online softmax update (row stats via width-16 shuffles) ----
#pragma unroll
        for (int i = 0; i < 4; i++) {
            float mt = fmaxf(fmaxf(s[i][0], s[i][1]), fmaxf(s[i][2], s[i][3]));
#pragma unroll
            for (int off = 8; off > 0; off >>= 1)
                mt = fmaxf(mt, __shfl_xor_sync(0xffffffffu, mt, off, 16));
            float m_new = fmaxf(m_i[i], mt);
            float alpha = __expf(m_i[i] - m_new);
            float rs = 0.0f;
#pragma unroll
            for (int j = 0; j < 4; j++) {
                s[i][j] = __expf(s[i][j] - m_new);
                rs += s[i][j];
            }
#pragma unroll
            for (int off = 8; off > 0; off >>= 1)
                rs += __shfl_xor_sync(0xffffffffu, rs, off, 16);
            l_i[i] = l_i[i] * alpha + rs;
            m_i[i] = m_new;
#pragma unroll
            for (int j = 0; j < 4; j++) acc[i][j] *= alpha;
        }

        __syncthreads();  // everyone done reading Ks before overwriting with P
#pragma unroll
        for (int i = 0; i < 4; i++)
            *(float4*)(Ks + (r0 + i) * FPAD + c0) =
                make_float4(s[i][0], s[i][1], s[i][2], s[i][3]);
        __syncthreads();

        // ---- acc += P @ V ----
#pragma unroll 4
        for (int c = 0; c < 64; c += 4) {
            float4 p4[4], v4[4];
#pragma unroll
            for (int i = 0; i < 4; i++)  p4[i]  = *(const float4*)(Ks + (r0 + i) * FPAD + c);
#pragma unroll
            for (int cc = 0; cc < 4; cc++) v4[cc] = *(const float4*)(Vs + (c + cc) * FPAD + c0);
#pragma unroll
            for (int i = 0; i < 4; i++) {
                const float pa[4] = {p4[i].x, p4[i].y, p4[i].z, p4[i].w};
#pragma unroll
                for (int cc = 0; cc < 4; cc++) {
                    const float va[4] = {v4[cc].x, v4[cc].y, v4[cc].z, v4[cc].w};
#pragma unroll
                    for (int j = 0; j < 4; j++)
                        acc[i][j] = fmaf(pa[cc], va[j], acc[i][j]);
                }
            }
        }
    }

    // ---- epilogue: normalize and store ----
    float* dst = O + (size_t)(qt * 64 + r0) * DM + h * DH + c0;
#pragma unroll
    for (int i = 0; i < 4; i++) {
        float inv = 1.0f / l_i[i];
        *(float4*)(dst + (size_t)i * DM) =
            make_float4(acc[i][0] * inv, acc[i][1] * inv, acc[i][2] * inv, acc[i][3] * inv);
    }
}

// ==============================================================================
// launch
// ==============================================================================
extern "C" void kernel_launch(void* const* d_in, const int* in_sizes, int n_in,
                              void* d_out, int out_size)
{
    const float* x     = (const float*)d_in[0];
    const float* W_q   = (const float*)d_in[1];
    const float* b_q   = (const float*)d_in[2];
    const float* W_kv  = (const float*)d_in[3];
    const float* b_kv  = (const float*)d_in[4];
    const float* W_out = (const float*)d_in[5];
    const float* b_out = (const float*)d_in[6];
    float* out = (float*)d_out;

    float *qbuf, *kvbuf, *abuf;
    cudaGetSymbolAddress((void**)&qbuf, g_Q);
    cudaGetSymbolAddress((void**)&kvbuf, g_KV);
    cudaGetSymbolAddress((void**)&abuf, g_attn);

    const int FA_SMEM = 3 * 64 * FPAD * sizeof(float);  // 52224 B
    cudaFuncSetAttribute(flash_attn, cudaFuncAttributeMaxDynamicSharedMemorySize, FA_SMEM);

    // Q projection: [2048,2048] = x @ W_q^T + b_q
    dim3 gq(DM / 128, S_LEN / 128);
    sgemm_nt_bias<<<gq, 256>>>(x, W_q, b_q, qbuf, S_LEN, DM, DM);

    // KV projection: [2048,1024] = x @ W_kv^T + b_kv
    dim3 gkv(KV_W / 128, S_LEN / 128);
    sgemm_nt_bias<<<gkv, 256>>>(x, W_kv, b_kv, kvbuf, S_LEN, KV_W, DM);

    // RoPE on Q (32 heads, stride 2048) and K half of KV (8 heads, stride 1024)
    rope_kernel<<<(S_LEN * QH * (DH / 2) + 255) / 256, 256>>>(qbuf, QH, DM);
    rope_kernel<<<(S_LEN * KVH * (DH / 2) + 255) / 256, 256>>>(kvbuf, KVH, KV_W);

    // Flash attention: grid = (32 q-tiles, 32 heads)
    flash_attn<<<dim3(S_LEN / 64, QH), 256, FA_SMEM>>>(qbuf, kvbuf, abuf);

    // Output projection: [2048,2048] = attn @ W_out^T + b_out
    sgemm_nt_bias<<<gq, 256>>>(abuf, W_out, b_out, out, S_LEN, DM, DM);
}

// round 3
// speedup vs baseline: 1.0005x; 1.0005x over previous
#include <cuda_runtime.h>
#include <math.h>

#define S_LEN 2048
#define DM    2048
#define QH    32
#define KVH   8
#define DH    64
#define KV_W  (2 * KVH * DH)   // 1024

// ---------------- scratch (allocation-free: __device__ globals) ----------------
__device__ float g_Q[S_LEN * DM];        // 16 MB: Q projections (rope'd in place)
__device__ float g_KV[S_LEN * KV_W];     //  8 MB: [K(512) | V(512)] per row
__device__ float g_attn[S_LEN * DM];     // 16 MB: attention output

// ==============================================================================
// SGEMM: C[M,N] = A[M,K] @ B[N,K]^T + bias[N]
// 128x128 block tile, BK=8, 256 threads, 8x8 per-thread register tile.
// All problem dims are multiples of 128/8 -> no bounds checks.
// ==============================================================================
__global__ __launch_bounds__(256, 2)
void sgemm_nt_bias(const float* __restrict__ A, const float* __restrict__ B,
                   const float* __restrict__ bias, float* __restrict__ C,
                   int M, int N, int K)
{
    __shared__ __align__(16) float As[8][128];
    __shared__ __align__(16) float Bs[8][128];

    const int tid  = threadIdx.x;
    const int brow = blockIdx.y * 128;
    const int bcol = blockIdx.x * 128;

    const int lr = tid >> 1;          // 0..127 : tile row loaded by this thread
    const int lk = (tid & 1) << 2;    // 0 or 4 : k offset (float4)
    const int tm = (tid >> 4) << 3;   // per-thread output rows
    const int tn = (tid & 15) << 3;   // per-thread output cols

    const float* Ap = A + (size_t)(brow + lr) * K + lk;
    const float* Bp = B + (size_t)(bcol + lr) * K + lk;

    float acc[8][8];
#pragma unroll
    for (int i = 0; i < 8; i++)
#pragma unroll
        for (int j = 0; j < 8; j++) acc[i][j] = 0.0f;

    for (int k0 = 0; k0 < K; k0 += 8) {
        float4 a4 = *(const float4*)Ap;
        float4 b4 = *(const float4*)Bp;
        As[lk + 0][lr] = a4.x; As[lk + 1][lr] = a4.y;
        As[lk + 2][lr] = a4.z; As[lk + 3][lr] = a4.w;
        Bs[lk + 0][lr] = b4.x; Bs[lk + 1][lr] = b4.y;
        Bs[lk + 2][lr] = b4.z; Bs[lk + 3][lr] = b4.w;
        __syncthreads();

#pragma unroll
        for (int k = 0; k < 8; k++) {
            float4 a0 = *(const float4*)&As[k][tm];
            float4 a1 = *(const float4*)&As[k][tm + 4];
            float4 b0 = *(const float4*)&Bs[k][tn];
            float4 b1 = *(const float4*)&Bs[k][tn + 4];
            const float ar[8] = {a0.x, a0.y, a0.z, a0.w, a1.x, a1.y, a1.z, a1.w};
            const float br[8] = {b0.x, b0.y, b0.z, b0.w, b1.x, b1.y, b1.z, b1.w};
#pragma unroll
            for (int i = 0; i < 8; i++)
#pragma unroll
                for (int j = 0; j < 8; j++)
                    acc[i][j] = fmaf(ar[i], br[j], acc[i][j]);
        }
        __syncthreads();
        Ap += 8;
        Bp += 8;
    }

#pragma unroll
    for (int i = 0; i < 8; i++) {
        float* Cp = C + (size_t)(brow + tm + i) * N + bcol + tn;
#pragma unroll
        for (int j = 0; j < 8; j += 4) {
            float4 v;
            v.x = acc[i][j + 0] + bias[bcol + tn + j + 0];
            v.y = acc[i][j + 1] + bias[bcol + tn + j + 1];
            v.z = acc[i][j + 2] + bias[bcol + tn + j + 2];
            v.w = acc[i][j + 3] + bias[bcol + tn + j + 3];
            *(float4*)(Cp + j) = v;
        }
    }
}

// ==============================================================================
// RoPE (interleaved pairs), in place. One thread per (s, head, pair).
// freq computed in double to match the fp32-rounded exact value jax produces.
// ==============================================================================
__global__ void rope_kernel(float* __restrict__ X, int H, int rowstride)
{
    int idx = blockIdx.x * blockDim.x + threadIdx.x;
    int total = S_LEN * H * (DH / 2);
    if (idx >= total) return;

    int j = idx & 31;           // pair index 0..31
    int t = idx >> 5;
    int h = t % H;
    int s = t / H;

    float freq  = (float)pow(10000.0, -(double)j / 32.0);
    float theta = (float)s * freq;
    float sn, cs;
    sincosf(theta, &sn, &cs);

    float* p = X + (size_t)s * rowstride + h * DH + 2 * j;
    float x1 = p[0], x2 = p[1];
    p[0] = x1 * cs - x2 * sn;
    p[1] = x1 * sn + x2 * cs;
}

// ==============================================================================
// Flash attention, fp32, no mask. One block per (q-tile of 64 rows, head).
// 256 threads as 16x16; each thread owns a 4x4 fragment.
// smem: Qs | Ks(reused as Ps) | Vs, each 64 x 68 floats (pad keeps 16B align).
// ==============================================================================
#define FPAD 68

__global__ __launch_bounds__(256)
void flash_attn(const float* __restrict__ Q, const float* __restrict__ KV,
                float* __restrict__ O)
{
    extern __shared__ float sm[];
    float* Qs = sm;                  // [64][FPAD]
    float* Ks = sm + 64 * FPAD;      // [64][FPAD], reused for P
    float* Vs = sm + 2 * 64 * FPAD;  // [64][FPAD]

    const int qt  = blockIdx.x;
    const int h   = blockIdx.y;
    const int hk  = h >> 2;          // grouped KV head
    const int tid = threadIdx.x;
    const int tx  = tid & 15;
    const int ty  = tid >> 4;
    const int r0  = ty << 2;         // 4 query rows
    const int c0  = tx << 2;         // 4 key cols / 4 output dims

    // ---- load Q tile, pre-scaled by 1/sqrt(64) ----
    {
        const float* src = Q + (size_t)(qt * 64) * DM + h * DH;
        for (int i = tid; i < 64 * 16; i += 256) {
            int r = i >> 4, c = (i & 15) << 2;
            float4 v = *(const float4*)(src + (size_t)r * DM + c);
            v.x *= 0.125f; v.y *= 0.125f; v.z *= 0.125f; v.w *= 0.125f;
            *(float4*)(Qs + r * FPAD + c) = v;
        }
    }

    float m_i[4], l_i[4], acc[4][4];
#pragma unroll
    for (int i = 0; i < 4; i++) {
        m_i[i] = -1e30f;
        l_i[i] = 0.0f;
#pragma unroll
        for (int j = 0; j < 4; j++) acc[i][j] = 0.0f;
    }

    for (int kt = 0; kt < 32; kt++) {
        __syncthreads();  // previous iteration done reading Ps/Vs (and 1st: no-op)

        // ---- load K, V tiles ----
        const float* ksrc = KV + (size_t)(kt * 64) * KV_W + hk * DH;
        const float* vsrc = ksrc + KVH * DH;  // V offset 512
        for (int i = tid; i < 64 * 16; i += 256) {
            int r = i >> 4, c = (i & 15) << 2;
            *(float4*)(Ks + r * FPAD + c) = *(const float4*)(ksrc + (size_t)r * KV_W + c);
            *(float4*)(Vs + r * FPAD + c) = *(const float4*)(vsrc + (size_t)r * KV_W + c);
        }
        __syncthreads();

        // ---- S = (Q*scale) @ K^T, 4x4 fragment ----
        float s[4][4];
#pragma unroll
        for (int i = 0; i < 4; i++)
#pragma unroll
            for (int j = 0; j < 4; j++) s[i][j] = 0.0f;

#pragma unroll 4
        for (int d = 0; d < 64; d += 4) {
            float4 q4[4], k4[4];
#pragma unroll
            for (int i = 0; i < 4; i++) q4[i] = *(const float4*)(Qs + (r0 + i) * FPAD + d);
#pragma unroll
            for (int j = 0; j < 4; j++) k4[j] = *(const float4*)(Ks + (c0 + j) * FPAD + d);
#pragma unroll
            for (int i = 0; i < 4; i++) {
                const float qa[4] = {q4[i].x, q4[i].y, q4[i].z, q4[i].w};
#pragma unroll
                for (int j = 0; j < 4; j++) {
                    const float ka[4] = {k4[j].x, k4[j].y, k4[j].z, k4[j].w};
#pragma unroll
                    for (int dd = 0; dd < 4; dd++)
                        s[i][j] = fmaf(qa[dd], ka[dd], s[i][j]);
                }
            }
        }

        // ---- online softmax update (row stats via width-16 shuffles) ----
#pragma unroll
        for (int i = 0; i < 4; i++) {
            float mt = fmaxf(fmaxf(s[i][0], s[i][1]), fmaxf(s[i][2], s[i][3]));
#pragma unroll
            for (int off = 8; off > 0; off >>= 1)
                mt = fmaxf(mt, __shfl_xor_sync(0xffffffffu, mt, off, 16));
            float m_new = fmaxf(m_i[i], mt);
            float alpha = __expf(m_i[i] - m_new);
            float rs = 0.0f;
#pragma unroll
            for (int j = 0; j < 4; j++) {
                s[i][j] = __expf(s[i][j] - m_new);
                rs += s[i][j];
            }
#pragma unroll
            for (int off = 8; off > 0; off >>= 1)
                rs += __shfl_xor_sync(0xffffffffu, rs, off, 16);
            l_i[i] = l_i[i] * alpha + rs;
            m_i[i] = m_new;
#pragma unroll
            for (int j = 0; j < 4; j++) acc[i][j] *= alpha;
        }

        __syncthreads();  // everyone done reading Ks before overwriting with P
#pragma unroll
        for (int i = 0; i < 4; i++)
            *(float4*)(Ks + (r0 + i) * FPAD + c0) =
                make_float4(s[i][0], s[i][1], s[i][2], s[i][3]);
        __syncthreads();

        // ---- acc += P @ V ----
#pragma unroll 4
        for (int c = 0; c < 64; c += 4) {
            float4 p4[4], v4[4];
#pragma unroll
            for (int i = 0; i < 4; i++)  p4[i]  = *(const float4*)(Ks + (r0 + i) * FPAD + c);
#pragma unroll
            for (int cc = 0; cc < 4; cc++) v4[cc] = *(const float4*)(Vs + (c + cc) * FPAD + c0);
#pragma unroll
            for (int i = 0; i < 4; i++) {
                const float pa[4] = {p4[i].x, p4[i].y, p4[i].z, p4[i].w};
#pragma unroll
                for (int cc = 0; cc < 4; cc++) {
                    const float va[4] = {v4[cc].x, v4[cc].y, v4[cc].z, v4[cc].w};
#pragma unroll
                    for (int j = 0; j < 4; j++)
                        acc[i][j] = fmaf(pa[cc], va[j], acc[i][j]);
                }
            }
        }
    }

    // ---- epilogue: normalize and store ----
    float* dst = O + (size_t)(qt * 64 + r0) * DM + h * DH + c0;
#pragma unroll
    for (int i = 0; i < 4; i++) {
        float inv = 1.0f / l_i[i];
        *(float4*)(dst + (size_t)i * DM) =
            make_float4(acc[i][0] * inv, acc[i][1] * inv, acc[i][2] * inv, acc[i][3] * inv);
    }
}

// ==============================================================================
// launch
// ==============================================================================
extern "C" void kernel_launch(void* const* d_in, const int* in_sizes, int n_in,
                              void* d_out, int out_size)
{
    const float* x     = (const float*)d_in[0];
    const float* W_q   = (const float*)d_in[1];
    const float* b_q   = (const float*)d_in[2];
    const float* W_kv  = (const float*)d_in[3];
    const float* b_kv  = (const float*)d_in[4];
    const float* W_out = (const float*)d_in[5];
    const float* b_out = (const float*)d_in[6];
    float* out = (float*)d_out;

    float *qbuf, *kvbuf, *abuf;
    cudaGetSymbolAddress((void**)&qbuf, g_Q);
    cudaGetSymbolAddress((void**)&kvbuf, g_KV);
    cudaGetSymbolAddress((void**)&abuf, g_attn);

    const int FA_SMEM = 3 * 64 * FPAD * sizeof(float);  // 52224 B
    cudaFuncSetAttribute(flash_attn, cudaFuncAttributeMaxDynamicSharedMemorySize, FA_SMEM);

    // Q projection: [2048,2048] = x @ W_q^T + b_q
    dim3 gq(DM / 128, S_LEN / 128);
    sgemm_nt_bias<<<gq, 256>>>(x, W_q, b_q, qbuf, S_LEN, DM, DM);

    // KV projection: [2048,1024] = x @ W_kv^T + b_kv
    dim3 gkv(KV_W / 128, S_LEN / 128);
    sgemm_nt_bias<<<gkv, 256>>>(x, W_kv, b_kv, kvbuf, S_LEN, KV_W, DM);

    // RoPE on Q (32 heads, stride 2048) and K half of KV (8 heads, stride 1024)
    rope_kernel<<<(S_LEN * QH * (DH / 2) + 255) / 256, 256>>>(qbuf, QH, DM);
    rope_kernel<<<(S_LEN * KVH * (DH / 2) + 255) / 256, 256>>>(kvbuf, KVH, KV_W);

    // Flash attention: grid = (32 q-tiles, 32 heads)
    flash_attn<<<dim3(S_LEN / 64, QH), 256, FA_SMEM>>>(qbuf, kvbuf, abuf);

    // Output projection: [2048,2048] = attn @ W_out^T + b_out
    sgemm_nt_bias<<<gq, 256>>>(abuf, W_out, b_out, out, S_LEN, DM, DM);
}

// round 5
// speedup vs baseline: 1.3252x; 1.3246x over previous
#include <cuda_runtime.h>
#include <math.h>
#include <stdint.h>

#define S_LEN 2048
#define DM    2048
#define QH    32
#define KVH   8
#define DH    64
#define KV_W  (2 * KVH * DH)   // 1024

// ---------------- scratch (allocation-free: __device__ globals) ----------------
__device__ float g_Q[S_LEN * DM];        // 16 MB
__device__ float g_KV[S_LEN * KV_W];     //  8 MB
__device__ float g_attn[S_LEN * DM];     // 16 MB
__device__ float g_freq[32];             // rope frequency table

// ============================ helpers ====================================
__device__ __forceinline__ uint32_t f2tf32(float x) {
    uint32_t r;
    asm("cvt.rna.tf32.f32 %0, %1;" : "=r"(r) : "f"(x));
    return r;
}

// D += A(16x8) * B(8x8), tf32 inputs, f32 accumulate. Standard sm_80+ mma.
__device__ __forceinline__ void mma_tf32(float* d,
                                         uint32_t a0, uint32_t a1, uint32_t a2, uint32_t a3,
                                         uint32_t b0, uint32_t b1) {
    asm volatile(
        "mma.sync.aligned.m16n8k8.row.col.f32.tf32.tf32.f32 "
        "{%0,%1,%2,%3}, {%4,%5,%6,%7}, {%8,%9}, {%0,%1,%2,%3};"
        : "+f"(d[0]), "+f"(d[1]), "+f"(d[2]), "+f"(d[3])
        : "r"(a0), "r"(a1), "r"(a2), "r"(a3), "r"(b0), "r"(b1));
}

// ==============================================================================
// 3xTF32 GEMM via mma.sync: C[M,N] = A[M,K] @ B[N,K]^T + bias[N]
// 128x128 CTA tile, BK=16, 256 threads (8 warps, 64x32 warp tiles).
// smem row stride 20 floats -> conflict-free quad fragment loads.
// A/B split hi/lo (tf32) on fill; 3 MMAs recover ~fp32 precision.
// ==============================================================================
#define BK     16
#define SSTR   20                 // smem row stride in floats
#define TILE_F (128 * SSTR)       // 2560 floats per matrix part
#define STAGE_F (4 * TILE_F)      // Ah | Al | Bh | Bl
#define TG_SMEM (2 * STAGE_F * 4) // bytes: 2 stages = 81920

__global__ __launch_bounds__(256, 2)
void tgemm_3xtf32_nt_bias(const float* __restrict__ A, const float* __restrict__ B,
                          const float* __restrict__ bias, float* __restrict__ C,
                          int M, int N, int K)
{
    extern __shared__ float sm[];

    const int tid  = threadIdx.x;
    const int wid  = tid >> 5;
    const int lane = tid & 31;
    const int qr   = lane >> 2;   // 0..7
    const int qc   = lane & 3;    // 0..3
    const int wm   = (wid & 1) * 64;    // warp rows
    const int wn   = (wid >> 1) * 32;   // warp cols
    const int brow = blockIdx.y * 128;
    const int bcol = blockIdx.x * 128;

    // gmem loader mapping: each thread owns row lr, 8 cols starting at lc
    const int lr = tid >> 1;
    const int lc = (tid & 1) * 8;
    const float* Ag = A + (size_t)(brow + lr) * K + lc;
    const float* Bg = B + (size_t)(bcol + lr) * K + lc;

    float acc[4][4][4];
#pragma unroll
    for (int mt = 0; mt < 4; mt++)
#pragma unroll
        for (int nt = 0; nt < 4; nt++)
#pragma unroll
            for (int i = 0; i < 4; i++) acc[mt][nt][i] = 0.0f;

    // split 8 floats into tf32 hi/lo and store to smem (16B-aligned uint4 stores)
    auto store8 = [&](float* hi, float* lo, float4 v0, float4 v1) {
        const int base = lr * SSTR + lc;
        float f[8] = {v0.x, v0.y, v0.z, v0.w, v1.x, v1.y, v1.z, v1.w};
        uint32_t h[8], l[8];
#pragma unroll
        for (int i = 0; i < 8; i++) {
            h[i] = f2tf32(f[i]);
            l[i] = f2tf32(f[i] - __uint_as_float(h[i]));
        }
        *(uint4*)&hi[base]     = make_uint4(h[0], h[1], h[2], h[3]);
        *(uint4*)&hi[base + 4] = make_uint4(h[4], h[5], h[6], h[7]);
        *(uint4*)&lo[base]     = make_uint4(l[0], l[1], l[2], l[3]);
        *(uint4*)&lo[base + 4] = make_uint4(l[4], l[5], l[6], l[7]);
    };

    // preload stage 0
    {
        float4 a0 = *(const float4*)Ag;
        float4 a1 = *(const float4*)(Ag + 4);
        float4 b0 = *(const float4*)Bg;
        float4 b1 = *(const float4*)(Bg + 4);
        store8(sm,              sm + TILE_F,     a0, a1);
        store8(sm + 2 * TILE_F, sm + 3 * TILE_F, b0, b1);
    }
    __syncthreads();

    const int NT = K / BK;
    float4 pa0, pa1, pb0, pb1;

    for (int kt = 0; kt < NT; kt++) {
        const int buf = kt & 1;

        if (kt + 1 < NT) {  // register prefetch of next stage
            const float* Ap = Ag + (kt + 1) * BK;
            const float* Bp = Bg + (kt + 1) * BK;
            pa0 = *(const float4*)Ap; pa1 = *(const float4*)(Ap + 4);
            pb0 = *(const float4*)Bp; pb1 = *(const float4*)(Bp + 4);
        }

        const float* Ah = sm + buf * STAGE_F;
        const float* Al = Ah + TILE_F;
        const float* Bh = Ah + 2 * TILE_F;
        const float* Bl = Ah + 3 * TILE_F;

#pragma unroll
        for (int ks = 0; ks < 2; ks++) {
            // B fragments (hi + lo) for 4 n-tiles
            uint32_t bh[4][2], bl[4][2];
#pragma unroll
            for (int nt = 0; nt < 4; nt++) {
                const int off = (wn + nt * 8 + qr) * SSTR + ks * 8 + qc;
                bh[nt][0] = __float_as_uint(Bh[off]);
                bh[nt][1] = __float_as_uint(Bh[off + 4]);
                bl[nt][0] = __float_as_uint(Bl[off]);
                bl[nt][1] = __float_as_uint(Bl[off + 4]);
            }
#pragma unroll
            for (int mt = 0; mt < 4; mt++) {
                const int off = (wm + mt * 16 + qr) * SSTR + ks * 8 + qc;
                uint32_t ah0 = __float_as_uint(Ah[off]);
                uint32_t ah1 = __float_as_uint(Ah[off + 8 * SSTR]);
                uint32_t ah2 = __float_as_uint(Ah[off + 4]);
                uint32_t ah3 = __float_as_uint(Ah[off + 8 * SSTR + 4]);
                uint32_t al0 = __float_as_uint(Al[off]);
                uint32_t al1 = __float_as_uint(Al[off + 8 * SSTR]);
                uint32_t al2 = __float_as_uint(Al[off + 4]);
                uint32_t al3 = __float_as_uint(Al[off + 8 * SSTR + 4]);
#pragma unroll
                for (int nt = 0; nt < 4; nt++) {
                    mma_tf32(acc[mt][nt], ah0, ah1, ah2, ah3, bh[nt][0], bh[nt][1]);
                    mma_tf32(acc[mt][nt], ah0, ah1, ah2, ah3, bl[nt][0], bl[nt][1]);
                    mma_tf32(acc[mt][nt], al0, al1, al2, al3, bh[nt][0], bh[nt][1]);
                }
            }
        }

        if (kt + 1 < NT) {
            __syncthreads();   // everyone done reading buf^1 (last read at kt-1) & this buf
            float* dst = sm + (buf ^ 1) * STAGE_F;
            store8(dst,              dst + TILE_F,     pa0, pa1);
            store8(dst + 2 * TILE_F, dst + 3 * TILE_F, pb0, pb1);
            __syncthreads();
        }
    }

    // epilogue: c0,c1 at (row, 2qc), c2,c3 at (row+8, 2qc)
#pragma unroll
    for (int mt = 0; mt < 4; mt++) {
        const int row = brow + wm + mt * 16 + qr;
#pragma unroll
        for (int nt = 0; nt < 4; nt++) {
            const int col = bcol + wn + nt * 8 + qc * 2;
            const float b0 = bias[col], b1 = bias[col + 1];
            *(float2*)(C + (size_t)row * N + col) =
                make_float2(acc[mt][nt][0] + b0, acc[mt][nt][1] + b1);
            *(float2*)(C + (size_t)(row + 8) * N + col) =
                make_float2(acc[mt][nt][2] + b0, acc[mt][nt][3] + b1);
        }
    }
}

// ==============================================================================
// RoPE: frequency table (exact double pow, once per launch) + apply kernel.
// ==============================================================================
__global__ void freq_kernel()
{
    int j = threadIdx.x;
    if (j < 32) g_freq[j] = (float)pow(10000.0, -(double)j / 32.0);
}

__global__ void rope_kernel(float* __restrict__ X, int H, int rowstride)
{
    int idx = blockIdx.x * blockDim.x + threadIdx.x;
    int total = S_LEN * H * (DH / 2);
    if (idx >= total) return;

    int j = idx & 31;
    int t = idx >> 5;
    int h = t % H;
    int s = t / H;

    float theta = (float)s * g_freq[j];
    float sn, cs;
    sincosf(theta, &sn, &cs);

    float* p = X + (size_t)s * rowstride + h * DH + 2 * j;
    float2 v = *(float2*)p;
    float2 o;
    o.x = v.x * cs - v.y * sn;
    o.y = v.x * sn + v.y * cs;
    *(float2*)p = o;
}

// ==============================================================================
// Flash attention, fp32 SIMT (known-good; mma.sync port next round).
// ==============================================================================
#define FPAD 68

__global__ __launch_bounds__(256)
void flash_attn(const float* __restrict__ Q, const float* __restrict__ KV,
                float* __restrict__ O)
{
    extern __shared__ float smf[];
    float* Qs = smf;
    float* Ks = smf + 64 * FPAD;
    float* Vs = smf + 2 * 64 * FPAD;

    const int qt  = blockIdx.x;
    const int h   = blockIdx.y;
    const int hk  = h >> 2;
    const int tid = threadIdx.x;
    const int tx  = tid & 15;
    const int ty  = tid >> 4;
    const int r0  = ty << 2;
    const int c0  = tx << 2;

    {
        const float* src = Q + (size_t)(qt * 64) * DM + h * DH;
        for (int i = tid; i < 64 * 16; i += 256) {
            int r = i >> 4, c = (i & 15) << 2;
            float4 v = *(const float4*)(src + (size_t)r * DM + c);
            v.x *= 0.125f; v.y *= 0.125f; v.z *= 0.125f; v.w *= 0.125f;
            *(float4*)(Qs + r * FPAD + c) = v;
        }
    }

    float m_i[4], l_i[4], acc[4][4];
#pragma unroll
    for (int i = 0; i < 4; i++) {
        m_i[i] = -1e30f;
        l_i[i] = 0.0f;
#pragma unroll
        for (int j = 0; j < 4; j++) acc[i][j] = 0.0f;
    }

    for (int kt = 0; kt < 32; kt++) {
        __syncthreads();

        const float* ksrc = KV + (size_t)(kt * 64) * KV_W + hk * DH;
        const float* vsrc = ksrc + KVH * DH;
        for (int i = tid; i < 64 * 16; i += 256) {
            int r = i >> 4, c = (i & 15) << 2;
            *(float4*)(Ks + r * FPAD + c) = *(const float4*)(ksrc + (size_t)r * KV_W + c);
            *(float4*)(Vs + r * FPAD + c) = *(const float4*)(vsrc + (size_t)r * KV_W + c);
        }
        __syncthreads();

        float s[4][4];
#pragma unroll
        for (int i = 0; i < 4; i++)
#pragma unroll
            for (int j = 0; j < 4; j++) s[i][j] = 0.0f;

#pragma unroll 4
        for (int d = 0; d < 64; d += 4) {
            float4 q4[4], k4[4];
#pragma unroll
            for (int i = 0; i < 4; i++) q4[i] = *(const float4*)(Qs + (r0 + i) * FPAD + d);
#pragma unroll
            for (int j = 0; j < 4; j++) k4[j] = *(const float4*)(Ks + (c0 + j) * FPAD + d);
#pragma unroll
            for (int i = 0; i < 4; i++) {
                const float qa[4] = {q4[i].x, q4[i].y, q4[i].z, q4[i].w};
#pragma unroll
                for (int j = 0; j < 4; j++) {
                    const float ka[4] = {k4[j].x, k4[j].y, k4[j].z, k4[j].w};
#pragma unroll
                    for (int dd = 0; dd < 4; dd++)
                        s[i][j] = fmaf(qa[dd], ka[dd], s[i][j]);
                }
            }
        }

#pragma unroll
        for (int i = 0; i < 4; i++) {
            float mt = fmaxf(fmaxf(s[i][0], s[i][1]), fmaxf(s[i][2], s[i][3]));
#pragma unroll
            for (int off = 8; off > 0; off >>= 1)
                mt = fmaxf(mt, __shfl_xor_sync(0xffffffffu, mt, off, 16));
            float m_new = fmaxf(m_i[i], mt);
            float alpha = __expf(m_i[i] - m_new);
            float rs = 0.0f;
#pragma unroll
            for (int j = 0; j < 4; j++) {
                s[i][j] = __expf(s[i][j] - m_new);
                rs += s[i][j];
            }
#pragma unroll
            for (int off = 8; off > 0; off >>= 1)
                rs += __shfl_xor_sync(0xffffffffu, rs, off, 16);
            l_i[i] = l_i[i] * alpha + rs;
            m_i[i] = m_new;
#pragma unroll
            for (int j = 0; j < 4; j++) acc[i][j] *= alpha;
        }

        __syncthreads();
#pragma unroll
        for (int i = 0; i < 4; i++)
            *(float4*)(Ks + (r0 + i) * FPAD + c0) =
                make_float4(s[i][0], s[i][1], s[i][2], s[i][3]);
        __syncthreads();

#pragma unroll 4
        for (int c = 0; c < 64; c += 4) {
            float4 p4[4], v4[4];
#pragma unroll
            for (int i = 0; i < 4; i++)  p4[i]  = *(const float4*)(Ks + (r0 + i) * FPAD + c);
#pragma unroll
            for (int cc = 0; cc < 4; cc++) v4[cc] = *(const float4*)(Vs + (c + cc) * FPAD + c0);
#pragma unroll
            for (int i = 0; i < 4; i++) {
                const float pa[4] = {p4[i].x, p4[i].y, p4[i].z, p4[i].w};
#pragma unroll
                for (int cc = 0; cc < 4; cc++) {
                    const float va[4] = {v4[cc].x, v4[cc].y, v4[cc].z, v4[cc].w};
#pragma unroll
                    for (int j = 0; j < 4; j++)
                        acc[i][j] = fmaf(pa[cc], va[j], acc[i][j]);
                }
            }
        }
    }

    float* dst = O + (size_t)(qt * 64 + r0) * DM + h * DH + c0;
#pragma unroll
    for (int i = 0; i < 4; i++) {
        float inv = 1.0f / l_i[i];
        *(float4*)(dst + (size_t)i * DM) =
            make_float4(acc[i][0] * inv, acc[i][1] * inv, acc[i][2] * inv, acc[i][3] * inv);
    }
}

// ==============================================================================
// launch
// ==============================================================================
extern "C" void kernel_launch(void* const* d_in, const int* in_sizes, int n_in,
                              void* d_out, int out_size)
{
    const float* x     = (const float*)d_in[0];
    const float* W_q   = (const float*)d_in[1];
    const float* b_q   = (const float*)d_in[2];
    const float* W_kv  = (const float*)d_in[3];
    const float* b_kv  = (const float*)d_in[4];
    const float* W_out = (const float*)d_in[5];
    const float* b_out = (const float*)d_in[6];
    float* out = (float*)d_out;

    float *qbuf, *kvbuf, *abuf;
    cudaGetSymbolAddress((void**)&qbuf, g_Q);
    cudaGetSymbolAddress((void**)&kvbuf, g_KV);
    cudaGetSymbolAddress((void**)&abuf, g_attn);

    const int FA_SMEM = 3 * 64 * FPAD * sizeof(float);
    cudaFuncSetAttribute(flash_attn, cudaFuncAttributeMaxDynamicSharedMemorySize, FA_SMEM);
    cudaFuncSetAttribute(tgemm_3xtf32_nt_bias, cudaFuncAttributeMaxDynamicSharedMemorySize, TG_SMEM);

    freq_kernel<<<1, 32>>>();

    // Q projection: [2048,2048]
    tgemm_3xtf32_nt_bias<<<dim3(DM / 128, S_LEN / 128), 256, TG_SMEM>>>(
        x, W_q, b_q, qbuf, S_LEN, DM, DM);

    // KV projection: [2048,1024]
    tgemm_3xtf32_nt_bias<<<dim3(KV_W / 128, S_LEN / 128), 256, TG_SMEM>>>(
        x, W_kv, b_kv, kvbuf, S_LEN, KV_W, DM);

    // RoPE
    rope_kernel<<<(S_LEN * QH * (DH / 2) + 255) / 256, 256>>>(qbuf, QH, DM);
    rope_kernel<<<(S_LEN * KVH * (DH / 2) + 255) / 256, 256>>>(kvbuf, KVH, KV_W);

    // Flash attention (SIMT fp32)
    flash_attn<<<dim3(S_LEN / 64, QH), 256, FA_SMEM>>>(qbuf, kvbuf, abuf);

    // Output projection: [2048,2048]
    tgemm_3xtf32_nt_bias<<<dim3(DM / 128, S_LEN / 128), 256, TG_SMEM>>>(
        abuf, W_out, b_out, out, S_LEN, DM, DM);
}

// round 6
// speedup vs baseline: 1.9640x; 1.4821x over previous
#include <cuda_runtime.h>
#include <math.h>
#include <stdint.h>

#define S_LEN 2048
#define DM    2048
#define QH    32
#define KVH   8
#define DH    64
#define KV_W  (2 * KVH * DH)   // 1024

// ---------------- scratch (allocation-free: __device__ globals) ----------------
__device__ float g_Q[S_LEN * DM];        // 16 MB
__device__ float g_KV[S_LEN * KV_W];     //  8 MB
__device__ float g_attn[S_LEN * DM];     // 16 MB
__device__ float g_freq[32];             // rope frequency table

// ============================ helpers ====================================
__device__ __forceinline__ uint32_t f2tf32(float x) {
    uint32_t r;
    asm("cvt.rna.tf32.f32 %0, %1;" : "=r"(r) : "f"(x));
    return r;
}

// D += A(16x8) * B(8x8), tf32 inputs, f32 accumulate (sm_80+ mma.sync).
__device__ __forceinline__ void mma_tf32(float* d,
                                         uint32_t a0, uint32_t a1, uint32_t a2, uint32_t a3,
                                         uint32_t b0, uint32_t b1) {
    asm volatile(
        "mma.sync.aligned.m16n8k8.row.col.f32.tf32.tf32.f32 "
        "{%0,%1,%2,%3}, {%4,%5,%6,%7}, {%8,%9}, {%0,%1,%2,%3};"
        : "+f"(d[0]), "+f"(d[1]), "+f"(d[2]), "+f"(d[3])
        : "r"(a0), "r"(a1), "r"(a2), "r"(a3), "r"(b0), "r"(b1));
}

// ==============================================================================
// 3xTF32 GEMM via mma.sync: C[M,N] = A[M,K] @ B[N,K]^T + bias[N]
// (unchanged from R4 — passing at rel_err 4.9e-5)
// ==============================================================================
#define BK     16
#define SSTR   20
#define TILE_F (128 * SSTR)
#define STAGE_F (4 * TILE_F)
#define TG_SMEM (2 * STAGE_F * 4)

__global__ __launch_bounds__(256, 2)
void tgemm_3xtf32_nt_bias(const float* __restrict__ A, const float* __restrict__ B,
                          const float* __restrict__ bias, float* __restrict__ C,
                          int M, int N, int K)
{
    extern __shared__ float sm[];

    const int tid  = threadIdx.x;
    const int wid  = tid >> 5;
    const int lane = tid & 31;
    const int qr   = lane >> 2;
    const int qc   = lane & 3;
    const int wm   = (wid & 1) * 64;
    const int wn   = (wid >> 1) * 32;
    const int brow = blockIdx.y * 128;
    const int bcol = blockIdx.x * 128;

    const int lr = tid >> 1;
    const int lc = (tid & 1) * 8;
    const float* Ag = A + (size_t)(brow + lr) * K + lc;
    const float* Bg = B + (size_t)(bcol + lr) * K + lc;

    float acc[4][4][4];
#pragma unroll
    for (int mt = 0; mt < 4; mt++)
#pragma unroll
        for (int nt = 0; nt < 4; nt++)
#pragma unroll
            for (int i = 0; i < 4; i++) acc[mt][nt][i] = 0.0f;

    auto store8 = [&](float* hi, float* lo, float4 v0, float4 v1) {
        const int base = lr * SSTR + lc;
        float f[8] = {v0.x, v0.y, v0.z, v0.w, v1.x, v1.y, v1.z, v1.w};
        uint32_t h[8], l[8];
#pragma unroll
        for (int i = 0; i < 8; i++) {
            h[i] = f2tf32(f[i]);
            l[i] = f2tf32(f[i] - __uint_as_float(h[i]));
        }
        *(uint4*)&hi[base]     = make_uint4(h[0], h[1], h[2], h[3]);
        *(uint4*)&hi[base + 4] = make_uint4(h[4], h[5], h[6], h[7]);
        *(uint4*)&lo[base]     = make_uint4(l[0], l[1], l[2], l[3]);
        *(uint4*)&lo[base + 4] = make_uint4(l[4], l[5], l[6], l[7]);
    };

    {
        float4 a0 = *(const float4*)Ag;
        float4 a1 = *(const float4*)(Ag + 4);
        float4 b0 = *(const float4*)Bg;
        float4 b1 = *(const float4*)(Bg + 4);
        store8(sm,              sm + TILE_F,     a0, a1);
        store8(sm + 2 * TILE_F, sm + 3 * TILE_F, b0, b1);
    }
    __syncthreads();

    const int NT = K / BK;
    float4 pa0, pa1, pb0, pb1;

    for (int kt = 0; kt < NT; kt++) {
        const int buf = kt & 1;

        if (kt + 1 < NT) {
            const float* Ap = Ag + (kt + 1) * BK;
            const float* Bp = Bg + (kt + 1) * BK;
            pa0 = *(const float4*)Ap; pa1 = *(const float4*)(Ap + 4);
            pb0 = *(const float4*)Bp; pb1 = *(const float4*)(Bp + 4);
        }

        const float* Ah = sm + buf * STAGE_F;
        const float* Al = Ah + TILE_F;
        const float* Bh = Ah + 2 * TILE_F;
        const float* Bl = Ah + 3 * TILE_F;

#pragma unroll
        for (int ks = 0; ks < 2; ks++) {
            uint32_t bh[4][2], bl[4][2];
#pragma unroll
            for (int nt = 0; nt < 4; nt++) {
                const int off = (wn + nt * 8 + qr) * SSTR + ks * 8 + qc;
                bh[nt][0] = __float_as_uint(Bh[off]);
                bh[nt][1] = __float_as_uint(Bh[off + 4]);
                bl[nt][0] = __float_as_uint(Bl[off]);
                bl[nt][1] = __float_as_uint(Bl[off + 4]);
            }
#pragma unroll
            for (int mt = 0; mt < 4; mt++) {
                const int off = (wm + mt * 16 + qr) * SSTR + ks * 8 + qc;
                uint32_t ah0 = __float_as_uint(Ah[off]);
                uint32_t ah1 = __float_as_uint(Ah[off + 8 * SSTR]);
                uint32_t ah2 = __float_as_uint(Ah[off + 4]);
                uint32_t ah3 = __float_as_uint(Ah[off + 8 * SSTR + 4]);
                uint32_t al0 = __float_as_uint(Al[off]);
                uint32_t al1 = __float_as_uint(Al[off + 8 * SSTR]);
                uint32_t al2 = __float_as_uint(Al[off + 4]);
                uint32_t al3 = __float_as_uint(Al[off + 8 * SSTR + 4]);
#pragma unroll
                for (int nt = 0; nt < 4; nt++) {
                    mma_tf32(acc[mt][nt], ah0, ah1, ah2, ah3, bh[nt][0], bh[nt][1]);
                    mma_tf32(acc[mt][nt], ah0, ah1, ah2, ah3, bl[nt][0], bl[nt][1]);
                    mma_tf32(acc[mt][nt], al0, al1, al2, al3, bh[nt][0], bh[nt][1]);
                }
            }
        }

        if (kt + 1 < NT) {
            __syncthreads();
            float* dst = sm + (buf ^ 1) * STAGE_F;
            store8(dst,              dst + TILE_F,     pa0, pa1);
            store8(dst + 2 * TILE_F, dst + 3 * TILE_F, pb0, pb1);
            __syncthreads();
        }
    }

#pragma unroll
    for (int mt = 0; mt < 4; mt++) {
        const int row = brow + wm + mt * 16 + qr;
#pragma unroll
        for (int nt = 0; nt < 4; nt++) {
            const int col = bcol + wn + nt * 8 + qc * 2;
            const float b0 = bias[col], b1 = bias[col + 1];
            *(float2*)(C + (size_t)row * N + col) =
                make_float2(acc[mt][nt][0] + b0, acc[mt][nt][1] + b1);
            *(float2*)(C + (size_t)(row + 8) * N + col) =
                make_float2(acc[mt][nt][2] + b0, acc[mt][nt][3] + b1);
        }
    }
}

// ==============================================================================
// RoPE
// ==============================================================================
__global__ void freq_kernel()
{
    int j = threadIdx.x;
    if (j < 32) g_freq[j] = (float)pow(10000.0, -(double)j / 32.0);
}

__global__ void rope_kernel(float* __restrict__ X, int H, int rowstride)
{
    int idx = blockIdx.x * blockDim.x + threadIdx.x;
    int total = S_LEN * H * (DH / 2);
    if (idx >= total) return;

    int j = idx & 31;
    int t = idx >> 5;
    int h = t % H;
    int s = t / H;

    float theta = (float)s * g_freq[j];
    float sn, cs;
    sincosf(theta, &sn, &cs);

    float* p = X + (size_t)s * rowstride + h * DH + 2 * j;
    float2 v = *(float2*)p;
    float2 o;
    o.x = v.x * cs - v.y * sn;
    o.y = v.x * sn + v.y * cs;
    *(float2*)p = o;
}

// ==============================================================================
// Flash attention on mma.sync tf32 with 3xTF32 compensation.
// Block = (64 q-rows, head). 128 threads = 4 warps; warp w owns rows w*16..+15.
// Q split hi/lo in smem (once); K/V/P stored fp32, split at fragment load.
// smem buffers stride 68 floats -> conflict-free fragment loads.
// ==============================================================================
#define FST   68
#define FBUF  (64 * FST)                 // 4352 floats
#define FA_SMEM (5 * FBUF * 4)           // Qh Ql Ks Vs Ps = 87040 B

__global__ __launch_bounds__(128, 2)
void flash_attn_mma(const float* __restrict__ Q, const float* __restrict__ KV,
                    float* __restrict__ O)
{
    extern __shared__ float smf[];
    float* Qh = smf;
    float* Ql = smf + FBUF;
    float* Ks = smf + 2 * FBUF;
    float* Vs = smf + 3 * FBUF;
    float* Ps = smf + 4 * FBUF;

    const int qt   = blockIdx.x;
    const int h    = blockIdx.y;
    const int hk   = h >> 2;
    const int tid  = threadIdx.x;
    const int wid  = tid >> 5;
    const int lane = tid & 31;
    const int qr   = lane >> 2;     // 0..7
    const int qc   = lane & 3;      // 0..3
    const int wm   = wid * 16;      // warp rows

    // ---- load Q tile (scaled by 1/8), split hi/lo ----
    {
        const float* src = Q + (size_t)(qt * 64) * DM + h * DH;
        for (int i = tid; i < 64 * 16; i += 128) {
            int r = i >> 4, c = (i & 15) << 2;
            float4 v = *(const float4*)(src + (size_t)r * DM + c);
            float f[4] = {v.x * 0.125f, v.y * 0.125f, v.z * 0.125f, v.w * 0.125f};
            uint32_t hh[4], ll[4];
#pragma unroll
            for (int j = 0; j < 4; j++) {
                hh[j] = f2tf32(f[j]);
                ll[j] = f2tf32(f[j] - __uint_as_float(hh[j]));
            }
            *(uint4*)&Qh[r * FST + c] = make_uint4(hh[0], hh[1], hh[2], hh[3]);
            *(uint4*)&Ql[r * FST + c] = make_uint4(ll[0], ll[1], ll[2], ll[3]);
        }
    }

    float m_i[2] = {-1e30f, -1e30f};
    float l_i[2] = {0.0f, 0.0f};
    float acc[8][4];
#pragma unroll
    for (int nt = 0; nt < 8; nt++)
#pragma unroll
        for (int i = 0; i < 4; i++) acc[nt][i] = 0.0f;

    for (int kt = 0; kt < 32; kt++) {
        __syncthreads();   // prior PV done reading Ks/Vs

        // ---- load K,V tiles (fp32) ----
        const float* ksrc = KV + (size_t)(kt * 64) * KV_W + hk * DH;
        const float* vsrc = ksrc + KVH * DH;
        for (int i = tid; i < 64 * 16; i += 128) {
            int r = i >> 4, c = (i & 15) << 2;
            *(float4*)(Ks + r * FST + c) = *(const float4*)(ksrc + (size_t)r * KV_W + c);
            *(float4*)(Vs + r * FST + c) = *(const float4*)(vsrc + (size_t)r * KV_W + c);
        }
        __syncthreads();

        // ---- S = Q @ K^T (3xTF32) ----
        float s[8][4];
#pragma unroll
        for (int nt = 0; nt < 8; nt++)
#pragma unroll
            for (int i = 0; i < 4; i++) s[nt][i] = 0.0f;

#pragma unroll
        for (int ks = 0; ks < 8; ks++) {
            const int aoff = (wm + qr) * FST + ks * 8 + qc;
            uint32_t qh0 = __float_as_uint(Qh[aoff]);
            uint32_t qh1 = __float_as_uint(Qh[aoff + 8 * FST]);
            uint32_t qh2 = __float_as_uint(Qh[aoff + 4]);
            uint32_t qh3 = __float_as_uint(Qh[aoff + 8 * FST + 4]);
            uint32_t ql0 = __float_as_uint(Ql[aoff]);
            uint32_t ql1 = __float_as_uint(Ql[aoff + 8 * FST]);
            uint32_t ql2 = __float_as_uint(Ql[aoff + 4]);
            uint32_t ql3 = __float_as_uint(Ql[aoff + 8 * FST + 4]);
#pragma unroll
            for (int nt = 0; nt < 8; nt++) {
                const int boff = (nt * 8 + qr) * FST + ks * 8 + qc;
                float f0 = Ks[boff], f1 = Ks[boff + 4];
                uint32_t kh0 = f2tf32(f0);
                uint32_t kh1 = f2tf32(f1);
                uint32_t kl0 = f2tf32(f0 - __uint_as_float(kh0));
                uint32_t kl1 = f2tf32(f1 - __uint_as_float(kh1));
                mma_tf32(s[nt], qh0, qh1, qh2, qh3, kh0, kh1);
                mma_tf32(s[nt], qh0, qh1, qh2, qh3, kl0, kl1);
                mma_tf32(s[nt], ql0, ql1, ql2, ql3, kh0, kh1);
            }
        }

        // ---- online softmax (rows qr and qr+8; quad reduction over qc) ----
#pragma unroll
        for (int half = 0; half < 2; half++) {
            float mt = -1e30f;
#pragma unroll
            for (int nt = 0; nt < 8; nt++)
                mt = fmaxf(mt, fmaxf(s[nt][2 * half], s[nt][2 * half + 1]));
            mt = fmaxf(mt, __shfl_xor_sync(0xffffffffu, mt, 1));
            mt = fmaxf(mt, __shfl_xor_sync(0xffffffffu, mt, 2));
            float m_new = fmaxf(m_i[half], mt);
            float alpha = __expf(m_i[half] - m_new);
            float rs = 0.0f;
#pragma unroll
            for (int nt = 0; nt < 8; nt++) {
                s[nt][2 * half]     = __expf(s[nt][2 * half] - m_new);
                s[nt][2 * half + 1] = __expf(s[nt][2 * half + 1] - m_new);
                rs += s[nt][2 * half] + s[nt][2 * half + 1];
            }
            rs += __shfl_xor_sync(0xffffffffu, rs, 1);
            rs += __shfl_xor_sync(0xffffffffu, rs, 2);
            l_i[half] = l_i[half] * alpha + rs;
            m_i[half] = m_new;
#pragma unroll
            for (int nt = 0; nt < 8; nt++) {
                acc[nt][2 * half]     *= alpha;
                acc[nt][2 * half + 1] *= alpha;
            }
        }

        // ---- write P (warp-private rows) ----
#pragma unroll
        for (int nt = 0; nt < 8; nt++) {
            *(float2*)&Ps[(wm + qr) * FST + nt * 8 + 2 * qc]     = make_float2(s[nt][0], s[nt][1]);
            *(float2*)&Ps[(wm + qr + 8) * FST + nt * 8 + 2 * qc] = make_float2(s[nt][2], s[nt][3]);
        }
        __syncwarp();

        // ---- acc += P @ V (3xTF32); B = V^T loaded from Vs[key][dim] ----
#pragma unroll
        for (int ks = 0; ks < 8; ks++) {
            const int poff = (wm + qr) * FST + ks * 8 + qc;
            float pf0 = Ps[poff];
            float pf1 = Ps[poff + 8 * FST];
            float pf2 = Ps[poff + 4];
            float pf3 = Ps[poff + 8 * FST + 4];
            uint32_t ph0 = f2tf32(pf0), ph1 = f2tf32(pf1);
            uint32_t ph2 = f2tf32(pf2), ph3 = f2tf32(pf3);
            uint32_t pl0 = f2tf32(pf0 - __uint_as_float(ph0));
            uint32_t pl1 = f2tf32(pf1 - __uint_as_float(ph1));
            uint32_t pl2 = f2tf32(pf2 - __uint_as_float(ph2));
            uint32_t pl3 = f2tf32(pf3 - __uint_as_float(ph3));
#pragma unroll
            for (int nt = 0; nt < 8; nt++) {
                float f0 = Vs[(ks * 8 + qc) * FST + nt * 8 + qr];
                float f1 = Vs[(ks * 8 + qc + 4) * FST + nt * 8 + qr];
                uint32_t vh0 = f2tf32(f0);
                uint32_t vh1 = f2tf32(f1);
                uint32_t vl0 = f2tf32(f0 - __uint_as_float(vh0));
                uint32_t vl1 = f2tf32(f1 - __uint_as_float(vh1));
                mma_tf32(acc[nt], ph0, ph1, ph2, ph3, vh0, vh1);
                mma_tf32(acc[nt], ph0, ph1, ph2, ph3, vl0, vl1);
                mma_tf32(acc[nt], pl0, pl1, pl2, pl3, vh0, vh1);
            }
        }
    }

    // ---- epilogue: normalize, store ----
    const float inv0 = 1.0f / l_i[0];
    const float inv1 = 1.0f / l_i[1];
    float* dst0 = O + (size_t)(qt * 64 + wm + qr) * DM + h * DH;
    float* dst1 = O + (size_t)(qt * 64 + wm + qr + 8) * DM + h * DH;
#pragma unroll
    for (int nt = 0; nt < 8; nt++) {
        *(float2*)(dst0 + nt * 8 + 2 * qc) = make_float2(acc[nt][0] * inv0, acc[nt][1] * inv0);
        *(float2*)(dst1 + nt * 8 + 2 * qc) = make_float2(acc[nt][2] * inv1, acc[nt][3] * inv1);
    }
}

// ==============================================================================
// launch
// ==============================================================================
extern "C" void kernel_launch(void* const* d_in, const int* in_sizes, int n_in,
                              void* d_out, int out_size)
{
    const float* x     = (const float*)d_in[0];
    const float* W_q   = (const float*)d_in[1];
    const float* b_q   = (const float*)d_in[2];
    const float* W_kv  = (const float*)d_in[3];
    const float* b_kv  = (const float*)d_in[4];
    const float* W_out = (const float*)d_in[5];
    const float* b_out = (const float*)d_in[6];
    float* out = (float*)d_out;

    float *qbuf, *kvbuf, *abuf;
    cudaGetSymbolAddress((void**)&qbuf, g_Q);
    cudaGetSymbolAddress((void**)&kvbuf, g_KV);
    cudaGetSymbolAddress((void**)&abuf, g_attn);

    cudaFuncSetAttribute(flash_attn_mma, cudaFuncAttributeMaxDynamicSharedMemorySize, FA_SMEM);
    cudaFuncSetAttribute(tgemm_3xtf32_nt_bias, cudaFuncAttributeMaxDynamicSharedMemorySize, TG_SMEM);

    freq_kernel<<<1, 32>>>();

    // Q projection: [2048,2048]
    tgemm_3xtf32_nt_bias<<<dim3(DM / 128, S_LEN / 128), 256, TG_SMEM>>>(
        x, W_q, b_q, qbuf, S_LEN, DM, DM);

    // KV projection: [2048,1024]
    tgemm_3xtf32_nt_bias<<<dim3(KV_W / 128, S_LEN / 128), 256, TG_SMEM>>>(
        x, W_kv, b_kv, kvbuf, S_LEN, KV_W, DM);

    // RoPE
    rope_kernel<<<(S_LEN * QH * (DH / 2) + 255) / 256, 256>>>(qbuf, QH, DM);
    rope_kernel<<<(S_LEN * KVH * (DH / 2) + 255) / 256, 256>>>(kvbuf, KVH, KV_W);

    // Flash attention (mma.sync tf32, 3x compensated)
    flash_attn_mma<<<dim3(S_LEN / 64, QH), 128, FA_SMEM>>>(qbuf, kvbuf, abuf);

    // Output projection: [2048,2048]
    tgemm_3xtf32_nt_bias<<<dim3(DM / 128, S_LEN / 128), 256, TG_SMEM>>>(
        abuf, W_out, b_out, out, S_LEN, DM, DM);
}